// round 15
// baseline (speedup 1.0000x reference)
#include <cuda_runtime.h>
#include <stdint.h>
#include <math.h>

// Problem constants
#define NBATCH 4
#define PREK   1024
#define NBUCK  65536      // 16-bit buckets of float bits (scores are positive)
#define CAP    2048       // candidate capacity per batch
#define MAXN   262144     // >= 200000
#define NEGBIG (-1e9f)

#define GEMV_BLOCKS 148   // single wave, 1 block/SM

// ---------------- device scratch (no allocations allowed) ----------------
__device__ float              g_raw[MAXN * 12];           // raw head outputs (11 used)
__device__ unsigned           g_sbits[MAXN];              // score as ordered uint
__device__ int                g_hist[NBATCH * NBUCK];     // per-batch histogram
__device__ int                g_cut[NBATCH];              // cutoff bucket
__device__ int                g_cnt[NBATCH];              // candidate counters
__device__ unsigned long long g_cand[NBATCH * CAP];       // (score_bits<<32)|(~idx)
__device__ float              g_vals[NBATCH * PREK];      // top-k scores
__device__ float              g_box7[NBATCH * PREK * 7];  // gathered boxes
__device__ float              g_x1[NBATCH * PREK], g_x2[NBATCH * PREK];
__device__ float              g_y1[NBATCH * PREK], g_y2[NBATCH * PREK];
__device__ float              g_ar[NBATCH * PREK];
__device__ unsigned           g_rows[NBATCH * PREK * 32]; // suppression bitmask rows
__device__ unsigned           g_rowAny[NBATCH * 32];      // rows with any overlap

// ---------------- packed f32x2 helpers (each half = independent rn op) ----
__device__ __forceinline__ unsigned long long pk2(float lo, float hi) {
    unsigned long long r;
    asm("mov.b64 %0, {%1, %2};" : "=l"(r) : "f"(lo), "f"(hi));
    return r;
}
__device__ __forceinline__ void upk2(unsigned long long v, float& lo, float& hi) {
    asm("mov.b64 {%0, %1}, %2;" : "=f"(lo), "=f"(hi) : "l"(v));
}
__device__ __forceinline__ unsigned long long ffma2(
    unsigned long long a, unsigned long long b, unsigned long long c) {
    unsigned long long d;
    asm("fma.rn.f32x2 %0, %1, %2, %3;" : "=l"(d) : "l"(a), "l"(b), "l"(c));
    return d;
}
__device__ __forceinline__ unsigned long long fadd2(
    unsigned long long a, unsigned long long b) {
    unsigned long long d;
    asm("add.rn.f32x2 %0, %1, %2;" : "=l"(d) : "l"(a), "l"(b), "l"(b));
    return d;
}

// correct fadd2 (above had a typo risk; define cleanly)
__device__ __forceinline__ unsigned long long fadd2v(
    unsigned long long a, unsigned long long b) {
    unsigned long long d;
    asm("add.rn.f32x2 %0, %1, %2;" : "=l"(d) : "l"(a), "l"(b));
    return d;
}

// ---------------- K1: GEMV 4 pts/warp + fused score/histogram ------------
// GEMV math bitwise-frozen (R14-passing 4-way split exchange).
// Score epilogue: lanes r3==6 (one per point) run the verbatim k_score
// sequence on s[0]/s[5] -> identical sbits. Also zeroes scratch counters.
__global__ __launch_bounds__(256) void k_gemv(
    const float* __restrict__ feat,
    const float* __restrict__ Wc, const float* __restrict__ Wr,
    const float* __restrict__ bc, const float* __restrict__ br,
    const int* __restrict__ bidx, int n)
{
    int gtid   = blockIdx.x * blockDim.x + threadIdx.x;
    int stride = gridDim.x * blockDim.x;
    for (int i = gtid; i < NBATCH * NBUCK; i += stride) g_hist[i] = 0;
    if (gtid < NBATCH)      g_cnt[gtid]  = 0;
    if (gtid < NBATCH * 32) g_rowAny[gtid] = 0;

    int lane  = threadIdx.x & 31;
    int warp  = gtid >> 5;
    int nwarp = stride >> 5;
    int c0 = lane * 8;

    unsigned long long wp[6][8];
#pragma unroll
    for (int i = 0; i < 8; i++) {
        wp[0][i] = pk2(Wc[(c0 + i) * 2 + 0], Wc[(c0 + i) * 2 + 1]);
        wp[1][i] = pk2(Wr[(c0 + i) * 9 + 0], Wr[(c0 + i) * 9 + 1]);
        wp[2][i] = pk2(Wr[(c0 + i) * 9 + 2], Wr[(c0 + i) * 9 + 3]);
        wp[3][i] = pk2(Wr[(c0 + i) * 9 + 4], Wr[(c0 + i) * 9 + 5]);
        wp[4][i] = pk2(Wr[(c0 + i) * 9 + 6], Wr[(c0 + i) * 9 + 7]);
        wp[5][i] = pk2(Wr[(c0 + i) * 9 + 8], 0.f);
    }
    float bc0 = bc[0], bc1 = bc[1], br8 = br[8];

    int nquad = (n + 3) >> 2;
    int pr = warp;
    if (pr >= nquad) return;

    float4 fA0, fA1, fB0, fB1, fC0, fC1, fD0, fD1;
    {
        int p0 = 4 * pr;
        int iA = p0, iB = min(p0 + 1, n - 1), iC = min(p0 + 2, n - 1), iD = min(p0 + 3, n - 1);
        const float* bA = feat + (size_t)iA * 256 + c0;
        const float* bB = feat + (size_t)iB * 256 + c0;
        const float* bC = feat + (size_t)iC * 256 + c0;
        const float* bD = feat + (size_t)iD * 256 + c0;
        fA0 = *(const float4*)bA; fA1 = *(const float4*)(bA + 4);
        fB0 = *(const float4*)bB; fB1 = *(const float4*)(bB + 4);
        fC0 = *(const float4*)bC; fC1 = *(const float4*)(bC + 4);
        fD0 = *(const float4*)bD; fD1 = *(const float4*)(bD + 4);
    }

    bool hi16 = (lane & 16) != 0;
    bool hi8  = (lane & 8)  != 0;
    int  r3   = lane & 7;
    int  pt   = lane >> 3;

    while (pr < nquad) {
        int prn = pr + nwarp;
        float4 nA0, nA1, nB0, nB1, nC0, nC1, nD0, nD1;
        if (prn < nquad) {               // prefetch next quad
            int q0 = 4 * prn;
            int iA = q0, iB = min(q0 + 1, n - 1), iC = min(q0 + 2, n - 1), iD = min(q0 + 3, n - 1);
            const float* bA = feat + (size_t)iA * 256 + c0;
            const float* bB = feat + (size_t)iB * 256 + c0;
            const float* bC = feat + (size_t)iC * 256 + c0;
            const float* bD = feat + (size_t)iD * 256 + c0;
            nA0 = *(const float4*)bA; nA1 = *(const float4*)(bA + 4);
            nB0 = *(const float4*)bB; nB1 = *(const float4*)(bB + 4);
            nC0 = *(const float4*)bC; nC1 = *(const float4*)(bC + 4);
            nD0 = *(const float4*)bD; nD1 = *(const float4*)(bD + 4);
        }

        float fvA[8] = {fA0.x, fA0.y, fA0.z, fA0.w, fA1.x, fA1.y, fA1.z, fA1.w};
        float fvB[8] = {fB0.x, fB0.y, fB0.z, fB0.w, fB1.x, fB1.y, fB1.z, fB1.w};
        float fvC[8] = {fC0.x, fC0.y, fC0.z, fC0.w, fC1.x, fC1.y, fC1.z, fC1.w};
        float fvD[8] = {fD0.x, fD0.y, fD0.z, fD0.w, fD1.x, fD1.y, fD1.z, fD1.w};

        unsigned long long aA[6], aB[6], aC[6], aD[6];
#pragma unroll
        for (int g = 0; g < 6; g++) { aA[g] = 0ULL; aB[g] = 0ULL; aC[g] = 0ULL; aD[g] = 0ULL; }
#pragma unroll
        for (int i = 0; i < 8; i++) {
            unsigned long long fa = pk2(fvA[i], fvA[i]);
            unsigned long long fb = pk2(fvB[i], fvB[i]);
            unsigned long long fc = pk2(fvC[i], fvC[i]);
            unsigned long long fd = pk2(fvD[i], fvD[i]);
#pragma unroll
            for (int g = 0; g < 6; g++) {
                unsigned long long wv = wp[g][i];
                aA[g] = ffma2(fa, wv, aA[g]);
                aB[g] = ffma2(fb, wv, aB[g]);
                aC[g] = ffma2(fc, wv, aC[g]);
                aD[g] = ffma2(fd, wv, aD[g]);
            }
        }

        unsigned long long t1[6], t2[6];
#pragma unroll
        for (int g = 0; g < 6; g++) {
            unsigned long long gv1 = hi16 ? aA[g] : aC[g];
            unsigned long long rv1 = __shfl_xor_sync(0xffffffffu, gv1, 16);
            unsigned long long k1  = hi16 ? aC[g] : aA[g];
            t1[g] = fadd2v(k1, rv1);
            unsigned long long gv2 = hi16 ? aB[g] : aD[g];
            unsigned long long rv2 = __shfl_xor_sync(0xffffffffu, gv2, 16);
            unsigned long long k2  = hi16 ? aD[g] : aB[g];
            t2[g] = fadd2v(k2, rv2);
        }
        unsigned long long s[6];
#pragma unroll
        for (int g = 0; g < 6; g++) {
            unsigned long long gv = hi8 ? t1[g] : t2[g];
            unsigned long long rv = __shfl_xor_sync(0xffffffffu, gv, 8);
            unsigned long long kp = hi8 ? t2[g] : t1[g];
            s[g] = fadd2v(kp, rv);
        }
#pragma unroll
        for (int off = 4; off >= 1; off >>= 1)
#pragma unroll
            for (int g = 0; g < 6; g++)
                s[g] = fadd2v(s[g], __shfl_xor_sync(0xffffffffu, s[g], off));

        int p = 4 * pr + pt;
        if (p < n) {
            unsigned long long sv = s[0];
#pragma unroll
            for (int g = 1; g < 6; g++) sv = (r3 == g) ? s[g] : sv;
            if (r3 < 6)
                *reinterpret_cast<unsigned long long*>(g_raw + (size_t)p * 12 + 2 * r3) = sv;
            if (r3 == 6) {
                // fused score (verbatim k_score sequence on same values)
                float a0, a1, a10, d;
                upk2(s[0], a0, a1);
                upk2(s[5], a10, d);
                float l0 = a0 + bc0, l1 = a1 + bc1;
                float conf = 1.f / (1.f + expf(l0 - l1));
                float r8v = a10 + br8;
                float scr = 1.f / (1.f + expf(-r8v));
                float score = conf * scr;
                unsigned sb = __float_as_uint(score);
                g_sbits[p] = sb;
                atomicAdd(&g_hist[bidx[p] * NBUCK + (sb >> 16)], 1);
            }
        }

        pr = prn;
        fA0 = nA0; fA1 = nA1; fB0 = nB0; fB1 = nB1;
        fC0 = nC0; fC1 = nC1; fD0 = nD0; fD1 = nD1;
    }
}

// ---------------- K2: cutoff — fully parallel suffix scans ----------------
__global__ __launch_bounds__(256) void k_cutoff() {
    __shared__ int sc[2][256];
    __shared__ int sAbove;
    __shared__ int sChunk;
    int b = blockIdx.x, t = threadIdx.x;

    const int4* h4 = reinterpret_cast<const int4*>(g_hist + b * NBUCK + t * 256);
    int s = 0;
#pragma unroll 8
    for (int i = 0; i < 64; i++) { int4 v = h4[i]; s += v.x + v.y + v.z + v.w; }

    int cur = 0, nxt = 1;
    sc[cur][t] = s;
    __syncthreads();
#pragma unroll
    for (int d = 1; d < 256; d <<= 1) {
        int v = sc[cur][t] + ((t + d < 256) ? sc[cur][t + d] : 0);
        sc[nxt][t] = v;
        __syncthreads();
        cur ^= 1; nxt ^= 1;
    }
    int Sincl = sc[cur][t];
    int Sexcl = (t + 1 < 256) ? sc[cur][t + 1] : 0;

    if (t == 0 && Sincl < PREK) { sChunk = 0; sAbove = 0; }
    if (Sincl >= PREK && Sexcl < PREK) { sChunk = t; sAbove = Sexcl; }
    __syncthreads();

    int chunk = sChunk, above = sAbove;
    int h = g_hist[b * NBUCK + chunk * 256 + t];
    sc[cur][t] = h;
    __syncthreads();
#pragma unroll
    for (int d = 1; d < 256; d <<= 1) {
        int v = sc[cur][t] + ((t + d < 256) ? sc[cur][t + d] : 0);
        sc[nxt][t] = v;
        __syncthreads();
        cur ^= 1; nxt ^= 1;
    }
    int inclK = above + sc[cur][t];
    int exclK = above + ((t + 1 < 256) ? sc[cur][t + 1] : 0);
    if (inclK >= PREK && exclK < PREK) g_cut[b] = chunk * 256 + t;
    if (t == 0 && above + sc[cur][0] < PREK) g_cut[b] = chunk * 256;
}

// ---------------- K3: compact candidates >= cutoff bucket (x4 vec) --------
__global__ void k_compact(const int* __restrict__ bidx, int n) {
    int q = blockIdx.x * blockDim.x + threadIdx.x;
    int i0 = q * 4;
    if (i0 >= n) return;
    if (i0 + 3 < n) {
        int4 bv = *reinterpret_cast<const int4*>(bidx + i0);
        uint4 sv = *reinterpret_cast<const uint4*>(g_sbits + i0);
        int bb[4] = {bv.x, bv.y, bv.z, bv.w};
        unsigned ss[4] = {sv.x, sv.y, sv.z, sv.w};
#pragma unroll
        for (int k = 0; k < 4; k++) {
            if ((int)(ss[k] >> 16) >= g_cut[bb[k]]) {
                int pos = atomicAdd(&g_cnt[bb[k]], 1);
                if (pos < CAP)
                    g_cand[bb[k] * CAP + pos] =
                        ((unsigned long long)ss[k] << 32) |
                        (unsigned long long)(0xFFFFFFFFu - (unsigned)(i0 + k));
            }
        }
    } else {
        for (int i = i0; i < n; i++) {
            int b = bidx[i];
            unsigned sb = g_sbits[i];
            if ((int)(sb >> 16) >= g_cut[b]) {
                int pos = atomicAdd(&g_cnt[b], 1);
                if (pos < CAP)
                    g_cand[b * CAP + pos] =
                        ((unsigned long long)sb << 32) |
                        (unsigned long long)(0xFFFFFFFFu - (unsigned)i);
            }
        }
    }
}

// ---------------- K4: per-batch bitonic sort + gather + box decode --------
__global__ __launch_bounds__(1024) void k_sort(
    const int* __restrict__ coor, const float* __restrict__ br, int n)
{
    __shared__ unsigned long long sk[CAP];
    int b = blockIdx.x, t = threadIdx.x;
    int cnt = g_cnt[b]; if (cnt > CAP) cnt = CAP;
#pragma unroll
    for (int r = 0; r < CAP / 1024; r++) {
        int i = t + r * 1024;
        sk[i] = (i < cnt) ? g_cand[b * CAP + i] : 0ULL;
    }
    __syncthreads();
    for (int k = 2; k <= CAP; k <<= 1) {
        for (int j = k >> 1; j > 0; j >>= 1) {
#pragma unroll
            for (int r = 0; r < CAP / 1024; r++) {
                int i = t + r * 1024;
                int l = i ^ j;
                if (l > i) {
                    unsigned long long A = sk[i], B = sk[l];
                    bool desc = ((i & k) == 0);
                    if (desc ? (A < B) : (A > B)) { sk[i] = B; sk[l] = A; }
                }
            }
            __syncthreads();
        }
    }
    if (t < PREK) {
        unsigned long long key = sk[t];
        unsigned idx = 0xFFFFFFFFu - (unsigned)(key & 0xFFFFFFFFull);
        float val = __uint_as_float((unsigned)(key >> 32));
        bool ok = (key != 0ULL) && (idx < (unsigned)n);
        float bx[7];
        if (ok) {
            const float* rp = g_raw + (size_t)idx * 12;
            float r0 = rp[2] + br[0], r1 = rp[3] + br[1], r2 = rp[4] + br[2];
            float r3 = rp[5] + br[3], r4v = rp[6] + br[4], r5 = rp[7] + br[5];
            float r6 = rp[8] + br[6], r7 = rp[9] + br[7];

            float cx = (float)coor[2 * idx]     * 0.8f + r0;
            float cy = (float)coor[2 * idx + 1] * 0.8f + r1;
            float L  = expf(fminf(fmaxf(r3,  -6.f), 6.f));
            float Wd = expf(fminf(fmaxf(r4v, -6.f), 6.f));
            float H  = expf(fminf(fmaxf(r5,  -6.f), 6.f));
            float ang = atan2f(r6, r7);

            bx[0] = cx; bx[1] = cy; bx[2] = r2;
            bx[3] = L;  bx[4] = Wd; bx[5] = H; bx[6] = ang;
        } else {
#pragma unroll
            for (int c = 0; c < 7; c++) bx[c] = 0.f;
            val = NEGBIG;
        }
        int o = b * PREK + t;
        g_vals[o] = val;
#pragma unroll
        for (int c = 0; c < 7; c++) g_box7[o * 7 + c] = bx[c];
        float hx = bx[3] * 0.5f, hy = bx[4] * 0.5f;
        g_x1[o] = bx[0] - hx; g_x2[o] = bx[0] + hx;
        g_y1[o] = bx[1] - hy; g_y2[o] = bx[1] + hy;
        g_ar[o] = bx[3] * bx[4];
    }
}

// ---------------- K5: iou — warp per (row, 32-col chunk), ballot ----------
__global__ __launch_bounds__(256) void k_iou() {
    int wtid = (blockIdx.x * blockDim.x + threadIdx.x) >> 5;
    int lane = threadIdx.x & 31;
    if (wtid >= NBATCH * PREK * 32) return;
    int b = wtid >> 15;
    int i = (wtid >> 5) & (PREK - 1);
    int c = wtid & 31;
    int o = b * PREK;
    int j = c * 32 + lane;

    unsigned w = 0;
    if (c * 32 + 31 > i) {
        float x1 = g_x1[o + i], x2 = g_x2[o + i];
        float y1 = g_y1[o + i], y2 = g_y2[o + i], ar = g_ar[o + i];
        bool hit = false;
        if (j > i) {
            float ix = fmaxf(fminf(x2, g_x2[o + j]) - fmaxf(x1, g_x1[o + j]), 0.f);
            float iy = fmaxf(fminf(y2, g_y2[o + j]) - fmaxf(y1, g_y1[o + j]), 0.f);
            float inter = ix * iy;
            float uni = ar + g_ar[o + j] - inter;
            hit = (inter / fmaxf(uni, 1e-6f)) > 0.1f;
        }
        w = __ballot_sync(0xffffffffu, hit);
    }
    if (lane == 0) {
        g_rows[((size_t)(o + i)) * 32 + c] = w;
        if (w) atomicOr(&g_rowAny[b * 32 + (i >> 5)], 1u << (i & 31));
    }
}

// ---------------- K6: sparse sequential NMS scan + output -----------------
__global__ __launch_bounds__(1024) void k_nms_out(float* __restrict__ out, int out_size) {
    __shared__ unsigned supp[32];
    int b = blockIdx.x, t = threadIdx.x;
    if (t < 32) {
        unsigned sup = 0;
        unsigned myAny = g_rowAny[b * 32 + t];
        for (int w = 0; w < 32; w++) {
            unsigned aw = __shfl_sync(0xffffffffu, myAny, w);
            while (aw) {
                int bit = __ffs(aw) - 1;
                aw &= aw - 1;
                int i = w * 32 + bit;
                unsigned sw = __shfl_sync(0xffffffffu, sup, i >> 5);
                if (!((sw >> (i & 31)) & 1u))
                    sup |= g_rows[((size_t)(b * PREK + i)) * 32 + t];
            }
        }
        supp[t] = sup;
    }
    __syncthreads();
    int o = b * PREK + t;
    float val = g_vals[o];
    bool valid = val > -5e8f;
    bool kp = valid && !((supp[t >> 5] >> (t & 31)) & 1u);
    float m = kp ? 1.f : 0.f;
    size_t base = (size_t)o * 8;
#pragma unroll
    for (int c = 0; c < 7; c++)
        if ((int)(base + c) < out_size) out[base + c] = g_box7[o * 7 + c] * m;
    if ((int)(base + 7) < out_size) out[base + 7] = val * m;
    size_t lbOff = (size_t)NBATCH * PREK * 8 + o;
    if ((int)lbOff < out_size) out[lbOff] = 0.f;
    size_t kpOff = (size_t)NBATCH * PREK * 9 + o;
    if ((int)kpOff < out_size) out[kpOff] = m;
}

// ---------------- launch ----------------
extern "C" void kernel_launch(void* const* d_in, const int* in_sizes, int n_in,
                              void* d_out, int out_size) {
    const float* feat = (const float*)d_in[0];
    const int*   bidx = (const int*)  d_in[1];
    const int*   coor = (const int*)  d_in[2];
    const float* Wc   = (const float*)d_in[3];
    const float* bc   = (const float*)d_in[4];
    const float* Wr   = (const float*)d_in[5];
    const float* br   = (const float*)d_in[6];
    int n = in_sizes[1];

    k_gemv   <<<GEMV_BLOCKS, 256>>>(feat, Wc, Wr, bc, br, bidx, n);  // + score/hist
    k_cutoff <<<NBATCH, 256>>>();
    k_compact<<<((n + 3) / 4 + 255) / 256, 256>>>(bidx, n);
    k_sort   <<<NBATCH, 1024>>>(coor, br, n);
    k_iou    <<<(NBATCH * PREK * 32 * 32 + 255) / 256, 256>>>();
    k_nms_out<<<NBATCH, 1024>>>((float*)d_out, out_size);
}

// round 16
// speedup vs baseline: 1.1075x; 1.1075x over previous
#include <cuda_runtime.h>
#include <stdint.h>
#include <math.h>

// Problem constants
#define NBATCH 4
#define PREK   1024
#define NBUCK  65536      // 16-bit buckets of float bits (scores are positive)
#define CAP    2048       // candidate capacity per batch
#define MAXN   262144     // >= 200000
#define NEGBIG (-1e9f)

#define GEMV_BLOCKS 148   // single wave, 1 block/SM

// ---------------- device scratch (no allocations allowed) ----------------
__device__ float              g_raw[MAXN * 12];           // raw head outputs (11 used)
__device__ float4             g_s3[MAXN];                 // (cls0, cls1, scr, pad) per point
__device__ unsigned           g_sbits[MAXN];              // score as ordered uint
__device__ int                g_hist[NBATCH * NBUCK];     // per-batch histogram
__device__ int                g_cut[NBATCH];              // cutoff bucket
__device__ int                g_cnt[NBATCH];              // candidate counters
__device__ unsigned long long g_cand[NBATCH * CAP];       // (score_bits<<32)|(~idx)
__device__ float              g_vals[NBATCH * PREK];      // top-k scores
__device__ float              g_box7[NBATCH * PREK * 7];  // gathered boxes
__device__ float              g_x1[NBATCH * PREK], g_x2[NBATCH * PREK];
__device__ float              g_y1[NBATCH * PREK], g_y2[NBATCH * PREK];
__device__ float              g_ar[NBATCH * PREK];
__device__ unsigned           g_rows[NBATCH * PREK * 32]; // suppression bitmask rows
__device__ unsigned           g_rowAny[NBATCH * 32];      // rows with any overlap

// ---------------- packed f32x2 helpers (each half = independent rn op) ----
__device__ __forceinline__ unsigned long long pk2(float lo, float hi) {
    unsigned long long r;
    asm("mov.b64 %0, {%1, %2};" : "=l"(r) : "f"(lo), "f"(hi));
    return r;
}
__device__ __forceinline__ void upk2(unsigned long long v, float& lo, float& hi) {
    asm("mov.b64 {%0, %1}, %2;" : "=f"(lo), "=f"(hi) : "l"(v));
}
__device__ __forceinline__ unsigned long long ffma2(
    unsigned long long a, unsigned long long b, unsigned long long c) {
    unsigned long long d;
    asm("fma.rn.f32x2 %0, %1, %2, %3;" : "=l"(d) : "l"(a), "l"(b), "l"(c));
    return d;
}
__device__ __forceinline__ unsigned long long fadd2v(
    unsigned long long a, unsigned long long b) {
    unsigned long long d;
    asm("add.rn.f32x2 %0, %1, %2;" : "=l"(d) : "l"(a), "l"(b));
    return d;
}

// ---------------- K1: GEMV, 4 points/warp (R14-passing, bitwise-frozen) ---
__global__ __launch_bounds__(256) void k_gemv(
    const float* __restrict__ feat,
    const float* __restrict__ Wc, const float* __restrict__ Wr, int n)
{
    int gtid   = blockIdx.x * blockDim.x + threadIdx.x;
    int stride = gridDim.x * blockDim.x;
    for (int i = gtid; i < NBATCH * NBUCK; i += stride) g_hist[i] = 0;
    if (gtid < NBATCH)      g_cnt[gtid]  = 0;
    if (gtid < NBATCH * 32) g_rowAny[gtid] = 0;

    int lane  = threadIdx.x & 31;
    int warp  = gtid >> 5;
    int nwarp = stride >> 5;
    int c0 = lane * 8;

    unsigned long long wp[6][8];
#pragma unroll
    for (int i = 0; i < 8; i++) {
        wp[0][i] = pk2(Wc[(c0 + i) * 2 + 0], Wc[(c0 + i) * 2 + 1]);
        wp[1][i] = pk2(Wr[(c0 + i) * 9 + 0], Wr[(c0 + i) * 9 + 1]);
        wp[2][i] = pk2(Wr[(c0 + i) * 9 + 2], Wr[(c0 + i) * 9 + 3]);
        wp[3][i] = pk2(Wr[(c0 + i) * 9 + 4], Wr[(c0 + i) * 9 + 5]);
        wp[4][i] = pk2(Wr[(c0 + i) * 9 + 6], Wr[(c0 + i) * 9 + 7]);
        wp[5][i] = pk2(Wr[(c0 + i) * 9 + 8], 0.f);
    }

    int nquad = (n + 3) >> 2;
    int pr = warp;
    if (pr >= nquad) return;

    float4 fA0, fA1, fB0, fB1, fC0, fC1, fD0, fD1;
    {
        int p0 = 4 * pr;
        int iA = p0, iB = min(p0 + 1, n - 1), iC = min(p0 + 2, n - 1), iD = min(p0 + 3, n - 1);
        const float* bA = feat + (size_t)iA * 256 + c0;
        const float* bB = feat + (size_t)iB * 256 + c0;
        const float* bC = feat + (size_t)iC * 256 + c0;
        const float* bD = feat + (size_t)iD * 256 + c0;
        fA0 = *(const float4*)bA; fA1 = *(const float4*)(bA + 4);
        fB0 = *(const float4*)bB; fB1 = *(const float4*)(bB + 4);
        fC0 = *(const float4*)bC; fC1 = *(const float4*)(bC + 4);
        fD0 = *(const float4*)bD; fD1 = *(const float4*)(bD + 4);
    }

    bool hi16 = (lane & 16) != 0;
    bool hi8  = (lane & 8)  != 0;
    int  r3   = lane & 7;
    int  pt   = lane >> 3;

    while (pr < nquad) {
        int prn = pr + nwarp;
        float4 nA0, nA1, nB0, nB1, nC0, nC1, nD0, nD1;
        if (prn < nquad) {               // prefetch next quad
            int q0 = 4 * prn;
            int iA = q0, iB = min(q0 + 1, n - 1), iC = min(q0 + 2, n - 1), iD = min(q0 + 3, n - 1);
            const float* bA = feat + (size_t)iA * 256 + c0;
            const float* bB = feat + (size_t)iB * 256 + c0;
            const float* bC = feat + (size_t)iC * 256 + c0;
            const float* bD = feat + (size_t)iD * 256 + c0;
            nA0 = *(const float4*)bA; nA1 = *(const float4*)(bA + 4);
            nB0 = *(const float4*)bB; nB1 = *(const float4*)(bB + 4);
            nC0 = *(const float4*)bC; nC1 = *(const float4*)(bC + 4);
            nD0 = *(const float4*)bD; nD1 = *(const float4*)(bD + 4);
        }

        float fvA[8] = {fA0.x, fA0.y, fA0.z, fA0.w, fA1.x, fA1.y, fA1.z, fA1.w};
        float fvB[8] = {fB0.x, fB0.y, fB0.z, fB0.w, fB1.x, fB1.y, fB1.z, fB1.w};
        float fvC[8] = {fC0.x, fC0.y, fC0.z, fC0.w, fC1.x, fC1.y, fC1.z, fC1.w};
        float fvD[8] = {fD0.x, fD0.y, fD0.z, fD0.w, fD1.x, fD1.y, fD1.z, fD1.w};

        unsigned long long aA[6], aB[6], aC[6], aD[6];
#pragma unroll
        for (int g = 0; g < 6; g++) { aA[g] = 0ULL; aB[g] = 0ULL; aC[g] = 0ULL; aD[g] = 0ULL; }
#pragma unroll
        for (int i = 0; i < 8; i++) {
            unsigned long long fa = pk2(fvA[i], fvA[i]);
            unsigned long long fb = pk2(fvB[i], fvB[i]);
            unsigned long long fc = pk2(fvC[i], fvC[i]);
            unsigned long long fd = pk2(fvD[i], fvD[i]);
#pragma unroll
            for (int g = 0; g < 6; g++) {
                unsigned long long wv = wp[g][i];
                aA[g] = ffma2(fa, wv, aA[g]);
                aB[g] = ffma2(fb, wv, aB[g]);
                aC[g] = ffma2(fc, wv, aC[g]);
                aD[g] = ffma2(fd, wv, aD[g]);
            }
        }

        unsigned long long t1[6], t2[6];
#pragma unroll
        for (int g = 0; g < 6; g++) {
            unsigned long long gv1 = hi16 ? aA[g] : aC[g];
            unsigned long long rv1 = __shfl_xor_sync(0xffffffffu, gv1, 16);
            unsigned long long k1  = hi16 ? aC[g] : aA[g];
            t1[g] = fadd2v(k1, rv1);
            unsigned long long gv2 = hi16 ? aB[g] : aD[g];
            unsigned long long rv2 = __shfl_xor_sync(0xffffffffu, gv2, 16);
            unsigned long long k2  = hi16 ? aD[g] : aB[g];
            t2[g] = fadd2v(k2, rv2);
        }
        unsigned long long s[6];
#pragma unroll
        for (int g = 0; g < 6; g++) {
            unsigned long long gv = hi8 ? t1[g] : t2[g];
            unsigned long long rv = __shfl_xor_sync(0xffffffffu, gv, 8);
            unsigned long long kp = hi8 ? t2[g] : t1[g];
            s[g] = fadd2v(kp, rv);
        }
#pragma unroll
        for (int off = 4; off >= 1; off >>= 1)
#pragma unroll
            for (int g = 0; g < 6; g++)
                s[g] = fadd2v(s[g], __shfl_xor_sync(0xffffffffu, s[g], off));

        int p = 4 * pr + pt;
        if (p < n) {
            unsigned long long sv = s[0];
#pragma unroll
            for (int g = 1; g < 6; g++) sv = (r3 == g) ? s[g] : sv;
            if (r3 < 6)
                *reinterpret_cast<unsigned long long*>(g_raw + (size_t)p * 12 + 2 * r3) = sv;
            if (r3 == 6) {
                float a0, a1, a10, d;
                upk2(s[0], a0, a1);
                upk2(s[5], a10, d);
                g_s3[p] = make_float4(a0, a1, a10, 0.f);
            }
        }

        pr = prn;
        fA0 = nA0; fA1 = nA1; fB0 = nB0; fB1 = nB1;
        fC0 = nC0; fC1 = nC1; fD0 = nD0; fD1 = nD1;
    }
}

// ---------------- K1b: score + histogram (thread per point, coalesced) ----
__global__ __launch_bounds__(256) void k_score(
    const int* __restrict__ bidx,
    const float* __restrict__ bc, const float* __restrict__ br, int n)
{
    int p = blockIdx.x * blockDim.x + threadIdx.x;
    if (p >= n) return;
    float4 sv = g_s3[p];

    float l0 = sv.x + bc[0], l1 = sv.y + bc[1];
    float conf = 1.f / (1.f + expf(l0 - l1));
    float r8 = sv.z + br[8];
    float scr = 1.f / (1.f + expf(-r8));
    float score = conf * scr;

    unsigned sb = __float_as_uint(score);
    g_sbits[p] = sb;
    atomicAdd(&g_hist[bidx[p] * NBUCK + (sb >> 16)], 1);
}

// ---------------- K2: cutoff — fully parallel suffix scans ----------------
__global__ __launch_bounds__(256) void k_cutoff() {
    __shared__ int sc[2][256];
    __shared__ int sAbove;
    __shared__ int sChunk;
    int b = blockIdx.x, t = threadIdx.x;

    const int4* h4 = reinterpret_cast<const int4*>(g_hist + b * NBUCK + t * 256);
    int s = 0;
#pragma unroll 8
    for (int i = 0; i < 64; i++) { int4 v = h4[i]; s += v.x + v.y + v.z + v.w; }

    int cur = 0, nxt = 1;
    sc[cur][t] = s;
    __syncthreads();
#pragma unroll
    for (int d = 1; d < 256; d <<= 1) {
        int v = sc[cur][t] + ((t + d < 256) ? sc[cur][t + d] : 0);
        sc[nxt][t] = v;
        __syncthreads();
        cur ^= 1; nxt ^= 1;
    }
    int Sincl = sc[cur][t];
    int Sexcl = (t + 1 < 256) ? sc[cur][t + 1] : 0;

    if (t == 0 && Sincl < PREK) { sChunk = 0; sAbove = 0; }
    if (Sincl >= PREK && Sexcl < PREK) { sChunk = t; sAbove = Sexcl; }
    __syncthreads();

    int chunk = sChunk, above = sAbove;
    int h = g_hist[b * NBUCK + chunk * 256 + t];
    sc[cur][t] = h;
    __syncthreads();
#pragma unroll
    for (int d = 1; d < 256; d <<= 1) {
        int v = sc[cur][t] + ((t + d < 256) ? sc[cur][t + d] : 0);
        sc[nxt][t] = v;
        __syncthreads();
        cur ^= 1; nxt ^= 1;
    }
    int inclK = above + sc[cur][t];
    int exclK = above + ((t + 1 < 256) ? sc[cur][t + 1] : 0);
    if (inclK >= PREK && exclK < PREK) g_cut[b] = chunk * 256 + t;
    if (t == 0 && above + sc[cur][0] < PREK) g_cut[b] = chunk * 256;
}

// ---------------- K3: compact candidates >= cutoff bucket (x4 vec) --------
__global__ void k_compact(const int* __restrict__ bidx, int n) {
    int q = blockIdx.x * blockDim.x + threadIdx.x;
    int i0 = q * 4;
    if (i0 >= n) return;
    if (i0 + 3 < n) {
        int4 bv = *reinterpret_cast<const int4*>(bidx + i0);
        uint4 sv = *reinterpret_cast<const uint4*>(g_sbits + i0);
        int bb[4] = {bv.x, bv.y, bv.z, bv.w};
        unsigned ss[4] = {sv.x, sv.y, sv.z, sv.w};
#pragma unroll
        for (int k = 0; k < 4; k++) {
            if ((int)(ss[k] >> 16) >= g_cut[bb[k]]) {
                int pos = atomicAdd(&g_cnt[bb[k]], 1);
                if (pos < CAP)
                    g_cand[bb[k] * CAP + pos] =
                        ((unsigned long long)ss[k] << 32) |
                        (unsigned long long)(0xFFFFFFFFu - (unsigned)(i0 + k));
            }
        }
    } else {
        for (int i = i0; i < n; i++) {
            int b = bidx[i];
            unsigned sb = g_sbits[i];
            if ((int)(sb >> 16) >= g_cut[b]) {
                int pos = atomicAdd(&g_cnt[b], 1);
                if (pos < CAP)
                    g_cand[b * CAP + pos] =
                        ((unsigned long long)sb << 32) |
                        (unsigned long long)(0xFFFFFFFFu - (unsigned)i);
            }
        }
    }
}

// ---------------- K4: hybrid register/shuffle bitonic sort + gather -------
// Same compare-exchange network as the smem bitonic (identical pairs and
// directions) -> identical sorted order. Phases with distance j<=16 run as
// 64-bit shuffles (no barriers); only j>=32 phases touch smem.
__global__ __launch_bounds__(1024) void k_sort(
    const int* __restrict__ coor, const float* __restrict__ br, int n)
{
    __shared__ unsigned long long sk[CAP];
    int b = blockIdx.x, t = threadIdx.x;
    int cnt = g_cnt[b]; if (cnt > CAP) cnt = CAP;

    unsigned long long v0 = (t < cnt)        ? g_cand[b * CAP + t]        : 0ULL;
    unsigned long long v1 = (t + 1024 < cnt) ? g_cand[b * CAP + t + 1024] : 0ULL;

    for (int k = 2; k <= CAP; k <<= 1) {
        if (k >= 64) {
            sk[t] = v0; sk[t + 1024] = v1;
            __syncthreads();
            for (int j = k >> 1; j >= 32; j >>= 1) {
#pragma unroll
                for (int r = 0; r < 2; r++) {
                    int i = t + r * 1024;
                    int l = i ^ j;
                    if (l > i) {
                        unsigned long long A = sk[i], B = sk[l];
                        bool desc = ((i & k) == 0);
                        if (desc ? (A < B) : (A > B)) { sk[i] = B; sk[l] = A; }
                    }
                }
                __syncthreads();
            }
            v0 = sk[t]; v1 = sk[t + 1024];
        }
        int jstart = ((k >> 1) < 16) ? (k >> 1) : 16;
        for (int j = jstart; j >= 1; j >>= 1) {
            {
                unsigned long long p = __shfl_xor_sync(0xffffffffu, v0, j);
                bool keepMax = (((t & j) == 0) == ((t & k) == 0));
                v0 = keepMax ? (v0 > p ? v0 : p) : (v0 < p ? v0 : p);
            }
            {
                int i = t + 1024;
                unsigned long long p = __shfl_xor_sync(0xffffffffu, v1, j);
                bool keepMax = (((i & j) == 0) == ((i & k) == 0));
                v1 = keepMax ? (v1 > p ? v1 : p) : (v1 < p ? v1 : p);
            }
        }
    }

    // gather top-1024: element t is v0 of thread t (sorted descending)
    {
        unsigned long long key = v0;
        unsigned idx = 0xFFFFFFFFu - (unsigned)(key & 0xFFFFFFFFull);
        float val = __uint_as_float((unsigned)(key >> 32));
        bool ok = (key != 0ULL) && (idx < (unsigned)n);
        float bx[7];
        if (ok) {
            const float* rp = g_raw + (size_t)idx * 12;
            float r0 = rp[2] + br[0], r1 = rp[3] + br[1], r2 = rp[4] + br[2];
            float r3 = rp[5] + br[3], r4v = rp[6] + br[4], r5 = rp[7] + br[5];
            float r6 = rp[8] + br[6], r7 = rp[9] + br[7];

            float cx = (float)coor[2 * idx]     * 0.8f + r0;
            float cy = (float)coor[2 * idx + 1] * 0.8f + r1;
            float L  = expf(fminf(fmaxf(r3,  -6.f), 6.f));
            float Wd = expf(fminf(fmaxf(r4v, -6.f), 6.f));
            float H  = expf(fminf(fmaxf(r5,  -6.f), 6.f));
            float ang = atan2f(r6, r7);

            bx[0] = cx; bx[1] = cy; bx[2] = r2;
            bx[3] = L;  bx[4] = Wd; bx[5] = H; bx[6] = ang;
        } else {
#pragma unroll
            for (int c = 0; c < 7; c++) bx[c] = 0.f;
            val = NEGBIG;
        }
        int o = b * PREK + t;
        g_vals[o] = val;
#pragma unroll
        for (int c = 0; c < 7; c++) g_box7[o * 7 + c] = bx[c];
        float hx = bx[3] * 0.5f, hy = bx[4] * 0.5f;
        g_x1[o] = bx[0] - hx; g_x2[o] = bx[0] + hx;
        g_y1[o] = bx[1] - hy; g_y2[o] = bx[1] + hy;
        g_ar[o] = bx[3] * bx[4];
    }
}

// ---------------- K5: iou — warp per (row, 32-col chunk), ballot ----------
__global__ __launch_bounds__(256) void k_iou() {
    int wtid = (blockIdx.x * blockDim.x + threadIdx.x) >> 5;
    int lane = threadIdx.x & 31;
    if (wtid >= NBATCH * PREK * 32) return;
    int b = wtid >> 15;
    int i = (wtid >> 5) & (PREK - 1);
    int c = wtid & 31;
    int o = b * PREK;
    int j = c * 32 + lane;

    unsigned w = 0;
    if (c * 32 + 31 > i) {
        float x1 = g_x1[o + i], x2 = g_x2[o + i];
        float y1 = g_y1[o + i], y2 = g_y2[o + i], ar = g_ar[o + i];
        bool hit = false;
        if (j > i) {
            float ix = fmaxf(fminf(x2, g_x2[o + j]) - fmaxf(x1, g_x1[o + j]), 0.f);
            float iy = fmaxf(fminf(y2, g_y2[o + j]) - fmaxf(y1, g_y1[o + j]), 0.f);
            float inter = ix * iy;
            float uni = ar + g_ar[o + j] - inter;
            hit = (inter / fmaxf(uni, 1e-6f)) > 0.1f;
        }
        w = __ballot_sync(0xffffffffu, hit);
    }
    if (lane == 0) {
        g_rows[((size_t)(o + i)) * 32 + c] = w;
        if (w) atomicOr(&g_rowAny[b * 32 + (i >> 5)], 1u << (i & 31));
    }
}

// ---------------- K6: sparse sequential NMS scan + output -----------------
__global__ __launch_bounds__(1024) void k_nms_out(float* __restrict__ out, int out_size) {
    __shared__ unsigned supp[32];
    int b = blockIdx.x, t = threadIdx.x;
    if (t < 32) {
        unsigned sup = 0;
        unsigned myAny = g_rowAny[b * 32 + t];
        for (int w = 0; w < 32; w++) {
            unsigned aw = __shfl_sync(0xffffffffu, myAny, w);
            while (aw) {
                int bit = __ffs(aw) - 1;
                aw &= aw - 1;
                int i = w * 32 + bit;
                unsigned sw = __shfl_sync(0xffffffffu, sup, i >> 5);
                if (!((sw >> (i & 31)) & 1u))
                    sup |= g_rows[((size_t)(b * PREK + i)) * 32 + t];
            }
        }
        supp[t] = sup;
    }
    __syncthreads();
    int o = b * PREK + t;
    float val = g_vals[o];
    bool valid = val > -5e8f;
    bool kp = valid && !((supp[t >> 5] >> (t & 31)) & 1u);
    float m = kp ? 1.f : 0.f;
    size_t base = (size_t)o * 8;
#pragma unroll
    for (int c = 0; c < 7; c++)
        if ((int)(base + c) < out_size) out[base + c] = g_box7[o * 7 + c] * m;
    if ((int)(base + 7) < out_size) out[base + 7] = val * m;
    size_t lbOff = (size_t)NBATCH * PREK * 8 + o;
    if ((int)lbOff < out_size) out[lbOff] = 0.f;
    size_t kpOff = (size_t)NBATCH * PREK * 9 + o;
    if ((int)kpOff < out_size) out[kpOff] = m;
}

// ---------------- launch ----------------
extern "C" void kernel_launch(void* const* d_in, const int* in_sizes, int n_in,
                              void* d_out, int out_size) {
    const float* feat = (const float*)d_in[0];
    const int*   bidx = (const int*)  d_in[1];
    const int*   coor = (const int*)  d_in[2];
    const float* Wc   = (const float*)d_in[3];
    const float* bc   = (const float*)d_in[4];
    const float* Wr   = (const float*)d_in[5];
    const float* br   = (const float*)d_in[6];
    int n = in_sizes[1];

    k_gemv   <<<GEMV_BLOCKS, 256>>>(feat, Wc, Wr, n);   // also zeroes scratch
    k_score  <<<(n + 255) / 256, 256>>>(bidx, bc, br, n);
    k_cutoff <<<NBATCH, 256>>>();
    k_compact<<<((n + 3) / 4 + 255) / 256, 256>>>(bidx, n);
    k_sort   <<<NBATCH, 1024>>>(coor, br, n);
    k_iou    <<<(NBATCH * PREK * 32 * 32 + 255) / 256, 256>>>();
    k_nms_out<<<NBATCH, 1024>>>((float*)d_out, out_size);
}